// round 15
// baseline (speedup 1.0000x reference)
#include <cuda_runtime.h>
#include <cuda_bf16.h>
#include <cstdint>

#define N_NODES 100000
#define N_EDGES 1600000
#define HID 128
#define SCAN_B 98

// ---------------- scratch (device globals; no allocation) ----------------
__device__ int   g_deg [N_NODES];
__device__ int   g_off [N_NODES];
__device__ int   g_cur [N_NODES];
__device__ int   g_bsum[128];
__device__ int   g_elist[N_EDGES];
__device__ int   g_dlist[N_EDGES];
__device__ int   g_eidl [N_EDGES];
__device__ float g_h1  [N_NODES * HID];
__device__ float g_agg2[N_NODES * HID];
__device__ float g_h2  [N_NODES * HID];
__device__ float g_p   [N_NODES * HID];
__device__ float g_q   [N_NODES * HID];

// ---------------- helpers ----------------
__device__ __forceinline__ uint32_t smem_u32(const void* p) {
    uint32_t a;
    asm("{ .reg .u64 t; cvta.to.shared.u64 t, %1; cvt.u32.u64 %0, t; }" : "=r"(a) : "l"(p));
    return a;
}
__device__ __forceinline__ void mma_tf32(float* d, const uint32_t* a, const uint32_t* b) {
    asm volatile(
        "mma.sync.aligned.m16n8k8.row.col.f32.tf32.tf32.f32 "
        "{%0,%1,%2,%3}, {%4,%5,%6,%7}, {%8,%9}, {%0,%1,%2,%3};"
        : "+f"(d[0]), "+f"(d[1]), "+f"(d[2]), "+f"(d[3])
        : "r"(a[0]), "r"(a[1]), "r"(a[2]), "r"(a[3]), "r"(b[0]), "r"(b[1]));
}
__device__ __forceinline__ void ldsm4(uint32_t* r, uint32_t addr) {
    asm volatile("ldmatrix.sync.aligned.m8n8.x4.shared.b16 {%0,%1,%2,%3}, [%4];"
                 : "=r"(r[0]), "=r"(r[1]), "=r"(r[2]), "=r"(r[3]) : "r"(addr));
}
__device__ __forceinline__ uint32_t cvt_tf32(float x) {
    uint32_t u;
    asm("cvt.rna.tf32.f32 %0, %1;" : "=r"(u) : "f"(x));
    return u;
}
#define NBAR_SYNC(id, n)   asm volatile("bar.sync %0, %1;"   :: "r"(id), "r"(n) : "memory")
#define NBAR_ARRIVE(id, n) asm volatile("bar.arrive %0, %1;" :: "r"(id), "r"(n) : "memory")

// ================== CSR build ==================
__global__ void k_zero_deg() {
    int i = blockIdx.x * 1024 + threadIdx.x;
    if (i < N_NODES) g_deg[i] = 0;
}
__global__ void k_hist(const int* __restrict__ ei) {
    int e = blockIdx.x * 256 + threadIdx.x;
    atomicAdd(&g_deg[ei[N_EDGES + e]], 1);
}
__global__ void k_scan1() {
    __shared__ int sh[1024];
    int tid = threadIdx.x;
    int i = blockIdx.x * 1024 + tid;
    int v = (i < N_NODES) ? g_deg[i] : 0;
    sh[tid] = v;
    __syncthreads();
#pragma unroll
    for (int ofs = 1; ofs < 1024; ofs <<= 1) {
        int o = (tid >= ofs) ? sh[tid - ofs] : 0;
        __syncthreads();
        sh[tid] += o;
        __syncthreads();
    }
    if (i < N_NODES) g_off[i] = sh[tid] - v;
    if (tid == 1023) g_bsum[blockIdx.x] = sh[1023];
}
__global__ void k_scan2() {
    __shared__ int sh[128];
    int t = threadIdx.x;
    int v = (t < SCAN_B) ? g_bsum[t] : 0;
    sh[t] = v;
    __syncthreads();
#pragma unroll
    for (int ofs = 1; ofs < 128; ofs <<= 1) {
        int o = (t >= ofs) ? sh[t - ofs] : 0;
        __syncthreads();
        sh[t] += o;
        __syncthreads();
    }
    if (t < SCAN_B) g_bsum[t] = sh[t] - v;
}
__global__ void k_scan3() {
    int i = blockIdx.x * 1024 + threadIdx.x;
    if (i < N_NODES) {
        int o = g_off[i] + g_bsum[blockIdx.x];
        g_off[i] = o;
        g_cur[i] = o;
    }
}
__global__ void k_scatter(const int* __restrict__ ei) {
    int e = blockIdx.x * 256 + threadIdx.x;
    int s = ei[e];
    int d = ei[N_EDGES + e];
    int pos = atomicAdd(&g_cur[d], 1);
    g_elist[pos] = s;
    g_dlist[pos] = d;
    g_eidl[pos] = e;
}

// ============ k_h1g: fused x-mean gather + h1 MLP (warp per node) ============
__global__ void k_h1g(const float* __restrict__ x,
                      const float* __restrict__ w1r, const float* __restrict__ w1n,
                      const float* __restrict__ b1) {
    int t = threadIdx.x;
    int lane = t & 31;
    int node = blockIdx.x * 8 + (t >> 5);

    float4 wr[6], wn[6];
#pragma unroll
    for (int k = 0; k < 6; k++) {
        wr[k] = *reinterpret_cast<const float4*>(&w1r[k * 128 + lane * 4]);
        wn[k] = *reinterpret_cast<const float4*>(&w1n[k * 128 + lane * 4]);
    }
    float4 bv = *reinterpret_cast<const float4*>(&b1[lane * 4]);

    int deg = g_deg[node];
    int off = g_off[node];

    float a0 = 0.f, a1 = 0.f, a2 = 0.f, a3 = 0.f, a4 = 0.f, a5 = 0.f;
    for (int i = lane; i < deg; i += 32) {
        int s = g_elist[off + i];
        const float2* xr = reinterpret_cast<const float2*>(x + s * 6);
        float2 v0 = xr[0], v1 = xr[1], v2 = xr[2];
        a0 += v0.x; a1 += v0.y; a2 += v1.x; a3 += v1.y; a4 += v2.x; a5 += v2.y;
    }
#pragma unroll
    for (int ofs = 16; ofs > 0; ofs >>= 1) {
        a0 += __shfl_xor_sync(0xffffffffu, a0, ofs);
        a1 += __shfl_xor_sync(0xffffffffu, a1, ofs);
        a2 += __shfl_xor_sync(0xffffffffu, a2, ofs);
        a3 += __shfl_xor_sync(0xffffffffu, a3, ofs);
        a4 += __shfl_xor_sync(0xffffffffu, a4, ofs);
        a5 += __shfl_xor_sync(0xffffffffu, a5, ofs);
    }
    float inv = 1.0f / fmaxf((float)deg, 1.0f);
    float m[6] = {a0 * inv, a1 * inv, a2 * inv, a3 * inv, a4 * inv, a5 * inv};

    const float2* xr = reinterpret_cast<const float2*>(x + node * 6);
    float2 x0 = xr[0], x1 = xr[1], x2 = xr[2];
    float xv[6] = {x0.x, x0.y, x1.x, x1.y, x2.x, x2.y};

    float4 h = bv;
#pragma unroll
    for (int k = 0; k < 6; k++) {
        h.x += xv[k] * wr[k].x + m[k] * wn[k].x;
        h.y += xv[k] * wr[k].y + m[k] * wn[k].y;
        h.z += xv[k] * wr[k].z + m[k] * wn[k].z;
        h.w += xv[k] * wr[k].w + m[k] * wn[k].w;
    }
    h.x = fmaxf(h.x, 0.f); h.y = fmaxf(h.y, 0.f);
    h.z = fmaxf(h.z, 0.f); h.w = fmaxf(h.w, 0.f);
    *reinterpret_cast<float4*>(&g_h1[(size_t)node * 128 + lane * 4]) = h;
}

// ============ k_gather2: mean of h1[srcs] -> g_agg2 (warp per node) ==========
__global__ void k_gather2() {
    int t = threadIdx.x;
    int lane = t & 31;
    int node = blockIdx.x * 8 + (t >> 5);
    int deg = g_deg[node];
    int off = g_off[node];

    float4 acc = make_float4(0.f, 0.f, 0.f, 0.f);
    int i = 0;
    for (; i + 4 <= deg; i += 4) {
        int s0 = g_elist[off + i + 0];
        int s1 = g_elist[off + i + 1];
        int s2 = g_elist[off + i + 2];
        int s3 = g_elist[off + i + 3];
        float4 v0 = *reinterpret_cast<const float4*>(&g_h1[(size_t)s0 * 128 + lane * 4]);
        float4 v1 = *reinterpret_cast<const float4*>(&g_h1[(size_t)s1 * 128 + lane * 4]);
        float4 v2 = *reinterpret_cast<const float4*>(&g_h1[(size_t)s2 * 128 + lane * 4]);
        float4 v3 = *reinterpret_cast<const float4*>(&g_h1[(size_t)s3 * 128 + lane * 4]);
        acc.x += v0.x + v1.x + v2.x + v3.x;
        acc.y += v0.y + v1.y + v2.y + v3.y;
        acc.z += v0.z + v1.z + v2.z + v3.z;
        acc.w += v0.w + v1.w + v2.w + v3.w;
    }
    for (; i < deg; i++) {
        int s = g_elist[off + i];
        float4 v = *reinterpret_cast<const float4*>(&g_h1[(size_t)s * 128 + lane * 4]);
        acc.x += v.x; acc.y += v.y; acc.z += v.z; acc.w += v.w;
    }
    float inv = 1.0f / fmaxf((float)deg, 1.0f);
    acc.x *= inv; acc.y *= inv; acc.z *= inv; acc.w *= inv;
    *reinterpret_cast<float4*>(&g_agg2[(size_t)node * 128 + lane * 4]) = acc;
}

// ================= k_h2_tf32 (unchanged) ======================================
#define H2_AS 0
#define H2_BS 9216
#define H2_TOTAL 75776

__global__ __launch_bounds__(256, 2)
void k_h2_tf32(const float* __restrict__ w2r, const float* __restrict__ w2n,
               const float* __restrict__ b2) {
    extern __shared__ __align__(16) char smem[];
    uint32_t smem_base = smem_u32(smem);
    int t = threadIdx.x, wid = t >> 5, lane = t & 31;
    int wm = wid >> 1;
    int wn = wid & 1;
    int row0 = blockIdx.x * 64;
    int nbase = blockIdx.y * 64;

#pragma unroll 8
    for (int i = 0; i < 64; i++) {
        int idx = i * 256 + t;
        int k = idx >> 6, n = idx & 63;
        float w = (k < 128) ? w2r[k * 128 + nbase + n]
                            : w2n[(k - 128) * 128 + nbase + n];
        *(uint32_t*)(smem + H2_BS + (uint32_t)n * 1040 + (uint32_t)k * 4) = cvt_tf32(w);
    }

    int arow_st = t >> 2;
    int akg = (t & 3) * 8;
    int grow_st = row0 + arow_st;
    bool valid = grow_st < N_NODES;

    int arow = lane & 15;
    uint32_t acolb = (lane & 16) ? 16u : 0u;
    int b_nrow = ((lane >> 4) << 3) + (lane & 7);
    uint32_t b_kb = ((lane >> 3) & 1) ? 16u : 0u;

    float acc[4][4] = {};

#pragma unroll 1
    for (int kc = 0; kc < 8; kc++) {
        {
            float v[8] = {0, 0, 0, 0, 0, 0, 0, 0};
            if (valid) {
                const float* src = (kc < 4)
                    ? &g_h1[(size_t)grow_st * 128 + kc * 32 + akg]
                    : &g_agg2[(size_t)grow_st * 128 + (kc - 4) * 32 + akg];
                float4 v0 = *reinterpret_cast<const float4*>(src);
                float4 v1 = *reinterpret_cast<const float4*>(src + 4);
                v[0] = v0.x; v[1] = v0.y; v[2] = v0.z; v[3] = v0.w;
                v[4] = v1.x; v[5] = v1.y; v[6] = v1.z; v[7] = v1.w;
            }
            uint4 t0, t1;
            t0.x = cvt_tf32(v[0]); t0.y = cvt_tf32(v[1]);
            t0.z = cvt_tf32(v[2]); t0.w = cvt_tf32(v[3]);
            t1.x = cvt_tf32(v[4]); t1.y = cvt_tf32(v[5]);
            t1.z = cvt_tf32(v[6]); t1.w = cvt_tf32(v[7]);
            char* dst = smem + H2_AS + (uint32_t)arow_st * 144 + (uint32_t)akg * 4;
            *(uint4*)(dst) = t0;
            *(uint4*)(dst + 16) = t1;
        }
        __syncthreads();

#pragma unroll
        for (int ks = 0; ks < 4; ks++) {
            uint32_t a[4];
            ldsm4(a, smem_base + H2_AS + (uint32_t)(wm * 16 + arow) * 144
                     + acolb + (uint32_t)ks * 32);
            uint32_t b01[4], b23[4];
            uint32_t boff = (uint32_t)(wn * 32 + b_nrow) * 1040 + b_kb
                          + (uint32_t)(kc * 32 + ks * 8) * 4;
            ldsm4(b01, smem_base + H2_BS + boff);
            ldsm4(b23, smem_base + H2_BS + boff + 16 * 1040);
            uint32_t* bf[4] = {b01, b01 + 2, b23, b23 + 2};
#pragma unroll
            for (int nn = 0; nn < 4; nn++) mma_tf32(acc[nn], a, bf[nn]);
        }
        __syncthreads();
    }

    int erow = row0 + wm * 16 + (lane >> 2);
    int ecol = nbase + wn * 32 + (lane & 3) * 2;
#pragma unroll
    for (int nn = 0; nn < 4; nn++) {
        int c = ecol + nn * 8;
        float b0 = b2[c], b1 = b2[c + 1];
        if (erow < N_NODES) {
            float2 o = make_float2(fmaxf(acc[nn][0] + b0, 0.f),
                                   fmaxf(acc[nn][1] + b1, 0.f));
            *reinterpret_cast<float2*>(&g_h2[(size_t)erow * 128 + c]) = o;
        }
        if (erow + 8 < N_NODES) {
            float2 o = make_float2(fmaxf(acc[nn][2] + b0, 0.f),
                                   fmaxf(acc[nn][3] + b1, 0.f));
            *reinterpret_cast<float2*>(&g_h2[(size_t)(erow + 8) * 128 + c]) = o;
        }
    }
}

// ================= k_pq_tf32 (unchanged) ======================================
#define PQ_AS 0
#define PQ_BS 9216
#define PQ_TOTAL 43008

__global__ __launch_bounds__(256, 2)
void k_pq_tf32(const float* __restrict__ we1) {
    extern __shared__ __align__(16) char smem[];
    uint32_t smem_base = smem_u32(smem);
    int t = threadIdx.x, wid = t >> 5, lane = t & 31;
    int wm = wid >> 1;
    int wn = wid & 1;
    int row0 = blockIdx.x * 64;
    int qtr = blockIdx.y;
    int nbase = (qtr & 1) * 64;
    int krow0 = (qtr < 2) ? 0 : 128;

#pragma unroll 8
    for (int i = 0; i < 32; i++) {
        int idx = i * 256 + t;
        int k = idx >> 6, n = idx & 63;
        float w = we1[(krow0 + k) * 128 + nbase + n];
        *(uint32_t*)(smem + PQ_BS + (uint32_t)n * 528 + (uint32_t)k * 4) = cvt_tf32(w);
    }

    int arow_st = t >> 2;
    int akg = (t & 3) * 8;
    int grow_st = row0 + arow_st;
    bool valid = grow_st < N_NODES;

    int arow = lane & 15;
    uint32_t acolb = (lane & 16) ? 16u : 0u;
    int b_nrow = ((lane >> 4) << 3) + (lane & 7);
    uint32_t b_kb = ((lane >> 3) & 1) ? 16u : 0u;

    float acc[4][4] = {};

#pragma unroll 1
    for (int kc = 0; kc < 4; kc++) {
        {
            float v[8] = {0, 0, 0, 0, 0, 0, 0, 0};
            if (valid) {
                const float* src = &g_h2[(size_t)grow_st * 128 + kc * 32 + akg];
                float4 v0 = *reinterpret_cast<const float4*>(src);
                float4 v1 = *reinterpret_cast<const float4*>(src + 4);
                v[0] = v0.x; v[1] = v0.y; v[2] = v0.z; v[3] = v0.w;
                v[4] = v1.x; v[5] = v1.y; v[6] = v1.z; v[7] = v1.w;
            }
            uint4 t0, t1;
            t0.x = cvt_tf32(v[0]); t0.y = cvt_tf32(v[1]);
            t0.z = cvt_tf32(v[2]); t0.w = cvt_tf32(v[3]);
            t1.x = cvt_tf32(v[4]); t1.y = cvt_tf32(v[5]);
            t1.z = cvt_tf32(v[6]); t1.w = cvt_tf32(v[7]);
            char* dst = smem + PQ_AS + (uint32_t)arow_st * 144 + (uint32_t)akg * 4;
            *(uint4*)(dst) = t0;
            *(uint4*)(dst + 16) = t1;
        }
        __syncthreads();

#pragma unroll
        for (int ks = 0; ks < 4; ks++) {
            uint32_t a[4];
            ldsm4(a, smem_base + PQ_AS + (uint32_t)(wm * 16 + arow) * 144
                     + acolb + (uint32_t)ks * 32);
            uint32_t b01[4], b23[4];
            uint32_t boff = (uint32_t)(wn * 32 + b_nrow) * 528 + b_kb
                          + (uint32_t)(kc * 32 + ks * 8) * 4;
            ldsm4(b01, smem_base + PQ_BS + boff);
            ldsm4(b23, smem_base + PQ_BS + boff + 16 * 528);
            uint32_t* bf[4] = {b01, b01 + 2, b23, b23 + 2};
#pragma unroll
            for (int nn = 0; nn < 4; nn++) mma_tf32(acc[nn], a, bf[nn]);
        }
        __syncthreads();
    }

    float* dstg = (qtr < 2) ? g_p : g_q;
    int erow = row0 + wm * 16 + (lane >> 2);
    int ecol = nbase + wn * 32 + (lane & 3) * 2;
#pragma unroll
    for (int nn = 0; nn < 4; nn++) {
        int c = ecol + nn * 8;
        if (erow < N_NODES)
            *reinterpret_cast<float2*>(&dstg[(size_t)erow * 128 + c]) =
                make_float2(acc[nn][0], acc[nn][1]);
        if (erow + 8 < N_NODES)
            *reinterpret_cast<float2*>(&dstg[(size_t)(erow + 8) * 128 + c]) =
                make_float2(acc[nn][2], acc[nn][3]);
    }
}

// ========== edge MLP: warp-specialized producer/consumer, tf32 mma ============
// Warps 0-7: gather+MLP+cvt into double-buffered A. Warps 8-15: mma+epilogue.
// Named-barrier ring: FULL(1,2) / EMPTY(3,4) at 512 arrivals; CONS(15) at 256.
#define SM_A      0                   // 2 * 128*528 = 135168
#define SM_B      135168              // 64*528 = 33792
#define SM_PA     168960              // float[2][128]
#define SM_PB     169984              // float[2][128]
#define SM_B2S    171008              // float[64]
#define SM_W3S    171264              // float[64]
#define SM_EDGE_TOTAL 171520
#define ABUF 67584

#define N_TILES (N_EDGES / 128)
#define EDGE_GRID 148

__global__ __launch_bounds__(512, 1)
void k_edge_ws(const float* __restrict__ ea,
               const float* __restrict__ we1, const float* __restrict__ be1,
               const float* __restrict__ we2, const float* __restrict__ be2,
               const float* __restrict__ we3, const float* __restrict__ be3,
               float* __restrict__ out) {
    extern __shared__ __align__(16) char smem[];
    uint32_t smem_base = smem_u32(smem);
    int t = threadIdx.x;
    int wid = t >> 5, lane = t & 31;

    float* paA = (float*)(smem + SM_PA);
    float* pbA = (float*)(smem + SM_PB);
    float* b2s = (float*)(smem + SM_B2S);
    float* w3s = (float*)(smem + SM_W3S);

    if (t < 64) { b2s[t] = be2[t]; w3s[t] = we3[t]; }
    // stage W2T (tf32) once
    for (int idx = t; idx < 64 * 128; idx += 512) {
        int n = idx >> 7, k = idx & 127;
        uint32_t w = cvt_tf32(we2[k * 64 + n]);
        *(uint32_t*)(smem + SM_B + (uint32_t)n * 528 + (uint32_t)k * 4) = w;
    }
    __syncthreads();

    if (wid < 8) {
        // ================= PRODUCER =================
        int kq = lane * 4;
        float4 b1v = *reinterpret_cast<const float4*>(&be1[kq]);
        float4 wc0 = *reinterpret_cast<const float4*>(&we1[256 * 128 + kq]);
        float4 wc1 = *reinterpret_cast<const float4*>(&we1[257 * 128 + kq]);
        float4 wc2 = *reinterpret_cast<const float4*>(&we1[258 * 128 + kq]);
        float4 wc3 = *reinterpret_cast<const float4*>(&we1[259 * 128 + kq]);

        int it = 0;
        for (int tile = blockIdx.x; tile < N_TILES; tile += EDGE_GRID) {
            int buf = it & 1;
            if (it >= 2) NBAR_SYNC(3 + buf, 512);
            int e0 = tile * 128;
            char* Ab = smem + SM_A + buf * ABUF;
#pragma unroll 4
            for (int i = 0; i < 16; i++) {
                int edge = i * 8 + wid;
                int pos = e0 + edge;
                int s = g_elist[pos];
                int d = g_dlist[pos];
                int eid = g_eidl[pos];
                float4 e4 = *reinterpret_cast<const float4*>(&ea[(size_t)eid * 4]);
                float4 pv = *reinterpret_cast<const float4*>(&g_p[(size_t)s * 128 + kq]);
                float4 qv = *reinterpret_cast<const float4*>(&g_q[(size_t)d * 128 + kq]);
                float v[4];
                v[0] = pv.x + qv.x + b1v.x + e4.x * wc0.x + e4.y * wc1.x + e4.z * wc2.x + e4.w * wc3.x;
                v[1] = pv.y + qv.y + b1v.y + e4.x * wc0.y + e4.y * wc1.y + e4.z * wc2.y + e4.w * wc3.y;
                v[2] = pv.z + qv.z + b1v.z + e4.x * wc0.z + e4.y * wc1.z + e4.z * wc2.z + e4.w * wc3.z;
                v[3] = pv.w + qv.w + b1v.w + e4.x * wc0.w + e4.y * wc1.w + e4.z * wc2.w + e4.w * wc3.w;
                uint4 tv;
                tv.x = cvt_tf32(fmaxf(v[0], 0.f));
                tv.y = cvt_tf32(fmaxf(v[1], 0.f));
                tv.z = cvt_tf32(fmaxf(v[2], 0.f));
                tv.w = cvt_tf32(fmaxf(v[3], 0.f));
                *(uint4*)(Ab + (uint32_t)edge * 528 + (uint32_t)kq * 4) = tv;
            }
            NBAR_ARRIVE(1 + buf, 512);
            it++;
        }
    } else {
        // ================= CONSUMER =================
        int cw = wid - 8;
        int wm = cw >> 1;             // 0..3 : rows wm*32..+31
        int wn = cw & 1;              // 0..1 : cols wn*32..+31
        float be3v = be3[0];

        int arow = lane & 15;
        uint32_t acolb = (lane & 16) ? 16u : 0u;
        int b_nrow = wn * 32 + ((lane >> 4) << 3) + (lane & 7);
        uint32_t b_kb = ((lane >> 3) & 1) ? 16u : 0u;
        uint32_t b_base = (uint32_t)b_nrow * 528 + b_kb;

        int it = 0;
        for (int tile = blockIdx.x; tile < N_TILES; tile += EDGE_GRID) {
            int buf = it & 1;
            NBAR_SYNC(1 + buf, 512);
            uint32_t Abase = smem_base + SM_A + buf * ABUF;

            float acc[2][4][4];
#pragma unroll
            for (int mi = 0; mi < 2; mi++)
#pragma unroll
                for (int nn = 0; nn < 4; nn++)
#pragma unroll
                    for (int r = 0; r < 4; r++) acc[mi][nn][r] = 0.f;

#pragma unroll
            for (int kk = 0; kk < 16; kk++) {
                uint32_t a0[4], a1[4];
                uint32_t aoff = (uint32_t)(wm * 32 + arow) * 528 + acolb + (uint32_t)kk * 32;
                ldsm4(a0, Abase + aoff);
                ldsm4(a1, Abase + aoff + 16 * 528);

                uint32_t b01[4], b23[4];
                uint32_t boff = b_base + (uint32_t)kk * 32;
                ldsm4(b01, smem_base + SM_B + boff);
                ldsm4(b23, smem_base + SM_B + boff + 16 * 528);
                uint32_t* bf[4] = {b01, b01 + 2, b23, b23 + 2};

#pragma unroll
                for (int nn = 0; nn < 4; nn++) {
                    mma_tf32(acc[0][nn], a0, bf[nn]);
                    mma_tf32(acc[1][nn], a1, bf[nn]);
                }
            }

            float part[2][2] = {{0.f, 0.f}, {0.f, 0.f}};
#pragma unroll
            for (int mi = 0; mi < 2; mi++) {
#pragma unroll
                for (int nn = 0; nn < 4; nn++) {
                    int c0 = wn * 32 + nn * 8 + (lane & 3) * 2;
                    float w30 = w3s[c0], w31 = w3s[c0 + 1];
                    float bb0 = b2s[c0], bb1 = b2s[c0 + 1];
                    part[mi][0] += fmaxf(acc[mi][nn][0] + bb0, 0.f) * w30
                                 + fmaxf(acc[mi][nn][1] + bb1, 0.f) * w31;
                    part[mi][1] += fmaxf(acc[mi][nn][2] + bb0, 0.f) * w30
                                 + fmaxf(acc[mi][nn][3] + bb1, 0.f) * w31;
                }
            }
#pragma unroll
            for (int mi = 0; mi < 2; mi++) {
#pragma unroll
                for (int g = 0; g < 2; g++) {
                    part[mi][g] += __shfl_xor_sync(0xffffffffu, part[mi][g], 1);
                    part[mi][g] += __shfl_xor_sync(0xffffffffu, part[mi][g], 2);
                }
            }
            if ((lane & 3) == 0) {
                float* pw = (wn ? pbA : paA) + buf * 128;
                int r0 = wm * 32 + (lane >> 2);
                pw[r0]      = part[0][0];
                pw[r0 + 8]  = part[0][1];
                pw[r0 + 16] = part[1][0];
                pw[r0 + 24] = part[1][1];
            }
            NBAR_SYNC(15, 256);
            int t2 = t - 256;
            if (t2 < 128) {
                int eid = g_eidl[tile * 128 + t2];
                out[eid] = paA[buf * 128 + t2] + pbA[buf * 128 + t2] + be3v;
            }
            NBAR_ARRIVE(3 + buf, 512);
            it++;
        }
    }
}

// ---------------- launch ----------------
extern "C" void kernel_launch(void* const* d_in, const int* in_sizes, int n_in,
                              void* d_out, int out_size) {
    const float* x   = (const float*)d_in[0];
    const int*   ei  = (const int*)d_in[1];
    const float* ea  = (const float*)d_in[2];
    const float* w1r = (const float*)d_in[3];
    const float* w1n = (const float*)d_in[4];
    const float* b1  = (const float*)d_in[5];
    const float* w2r = (const float*)d_in[6];
    const float* w2n = (const float*)d_in[7];
    const float* b2  = (const float*)d_in[8];
    const float* we1 = (const float*)d_in[9];
    const float* be1 = (const float*)d_in[10];
    const float* we2 = (const float*)d_in[11];
    const float* be2 = (const float*)d_in[12];
    const float* we3 = (const float*)d_in[13];
    const float* be3 = (const float*)d_in[14];
    float* out = (float*)d_out;

    cudaFuncSetAttribute(k_h2_tf32, cudaFuncAttributeMaxDynamicSharedMemorySize,
                         H2_TOTAL);
    cudaFuncSetAttribute(k_pq_tf32, cudaFuncAttributeMaxDynamicSharedMemorySize,
                         PQ_TOTAL);
    cudaFuncSetAttribute(k_edge_ws, cudaFuncAttributeMaxDynamicSharedMemorySize,
                         SM_EDGE_TOTAL);

    // CSR build
    k_zero_deg<<<SCAN_B, 1024>>>();
    k_hist<<<N_EDGES / 256, 256>>>(ei);
    k_scan1<<<SCAN_B, 1024>>>();
    k_scan2<<<1, 128>>>();
    k_scan3<<<SCAN_B, 1024>>>();
    k_scatter<<<N_EDGES / 256, 256>>>(ei);
    // node pipeline
    k_h1g<<<N_NODES / 8, 256>>>(x, w1r, w1n, b1);
    k_gather2<<<N_NODES / 8, 256>>>();
    k_h2_tf32<<<dim3((N_NODES + 63) / 64, 2), 256, H2_TOTAL>>>(w2r, w2n, b2);
    k_pq_tf32<<<dim3((N_NODES + 63) / 64, 4), 256, PQ_TOTAL>>>(we1);
    // edge pipeline
    k_edge_ws<<<EDGE_GRID, 512, SM_EDGE_TOTAL>>>(ea, we1, be1, we2, be2, we3, be3, out);
}

// round 16
// speedup vs baseline: 1.1011x; 1.1011x over previous
#include <cuda_runtime.h>
#include <cuda_bf16.h>
#include <cuda_fp16.h>
#include <cstdint>

#define N_NODES 100000
#define N_EDGES 1600000
#define HID 128
#define SCAN_B 98                    // ceil(100000/1024)

// ---------------- scratch (device globals; no allocation) ----------------
__device__ int   g_deg [N_NODES];
__device__ int   g_off [N_NODES];
__device__ int   g_cur [N_NODES];
__device__ int   g_bsum[128];
__device__ int   g_elist[N_EDGES];   // src ids grouped by dst
__device__ int   g_dlist[N_EDGES];   // dst id per CSR position
__device__ int   g_eidl [N_EDGES];   // original edge id per CSR position
__device__ float g_h1  [N_NODES * HID];
__device__ float g_agg2[N_NODES * HID];   // mean of h1 over in-edges
__device__ float g_h2  [N_NODES * HID];
__device__ __half g_p  [N_NODES * HID];   // h2 @ W_e1[0:128], fp16
__device__ float g_q   [N_NODES * HID];   // h2 @ W_e1[128:256], fp32

// ---------------- warp MMA helpers (baseline PTX) ----------------
__device__ __forceinline__ uint32_t smem_u32(const void* p) {
    uint32_t a;
    asm("{ .reg .u64 t; cvta.to.shared.u64 t, %1; cvt.u32.u64 %0, t; }" : "=r"(a) : "l"(p));
    return a;
}
__device__ __forceinline__ void mma_tf32(float* d, const uint32_t* a, const uint32_t* b) {
    asm volatile(
        "mma.sync.aligned.m16n8k8.row.col.f32.tf32.tf32.f32 "
        "{%0,%1,%2,%3}, {%4,%5,%6,%7}, {%8,%9}, {%0,%1,%2,%3};"
        : "+f"(d[0]), "+f"(d[1]), "+f"(d[2]), "+f"(d[3])
        : "r"(a[0]), "r"(a[1]), "r"(a[2]), "r"(a[3]), "r"(b[0]), "r"(b[1]));
}
__device__ __forceinline__ void ldsm4(uint32_t* r, uint32_t addr) {
    asm volatile("ldmatrix.sync.aligned.m8n8.x4.shared.b16 {%0,%1,%2,%3}, [%4];"
                 : "=r"(r[0]), "=r"(r[1]), "=r"(r[2]), "=r"(r[3]) : "r"(addr));
}
__device__ __forceinline__ uint32_t cvt_tf32(float x) {
    uint32_t u;
    asm("cvt.rna.tf32.f32 %0, %1;" : "=r"(u) : "f"(x));
    return u;
}

// ================== CSR build ==================
__global__ void k_zero_deg() {
    int i = blockIdx.x * 1024 + threadIdx.x;
    if (i < N_NODES) g_deg[i] = 0;
}
__global__ void k_hist(const int* __restrict__ ei) {
    int e = blockIdx.x * 256 + threadIdx.x;
    atomicAdd(&g_deg[ei[N_EDGES + e]], 1);
}
__global__ void k_scan1() {
    __shared__ int sh[1024];
    int tid = threadIdx.x;
    int i = blockIdx.x * 1024 + tid;
    int v = (i < N_NODES) ? g_deg[i] : 0;
    sh[tid] = v;
    __syncthreads();
#pragma unroll
    for (int ofs = 1; ofs < 1024; ofs <<= 1) {
        int o = (tid >= ofs) ? sh[tid - ofs] : 0;
        __syncthreads();
        sh[tid] += o;
        __syncthreads();
    }
    if (i < N_NODES) g_off[i] = sh[tid] - v;
    if (tid == 1023) g_bsum[blockIdx.x] = sh[1023];
}
__global__ void k_scan2() {
    __shared__ int sh[128];
    int t = threadIdx.x;
    int v = (t < SCAN_B) ? g_bsum[t] : 0;
    sh[t] = v;
    __syncthreads();
#pragma unroll
    for (int ofs = 1; ofs < 128; ofs <<= 1) {
        int o = (t >= ofs) ? sh[t - ofs] : 0;
        __syncthreads();
        sh[t] += o;
        __syncthreads();
    }
    if (t < SCAN_B) g_bsum[t] = sh[t] - v;
}
__global__ void k_scan3() {
    int i = blockIdx.x * 1024 + threadIdx.x;
    if (i < N_NODES) {
        int o = g_off[i] + g_bsum[blockIdx.x];
        g_off[i] = o;
        g_cur[i] = o;
    }
}
__global__ void k_scatter(const int* __restrict__ ei) {
    int e = blockIdx.x * 256 + threadIdx.x;
    int s = ei[e];
    int d = ei[N_EDGES + e];
    int pos = atomicAdd(&g_cur[d], 1);
    g_elist[pos] = s;
    g_dlist[pos] = d;
    g_eidl[pos] = e;
}

// ============ k_h1g: fused x-mean gather + h1 MLP (warp per node) ============
__global__ void k_h1g(const float* __restrict__ x,
                      const float* __restrict__ w1r, const float* __restrict__ w1n,
                      const float* __restrict__ b1) {
    int t = threadIdx.x;
    int lane = t & 31;
    int node = blockIdx.x * 8 + (t >> 5);

    float4 wr[6], wn[6];
#pragma unroll
    for (int k = 0; k < 6; k++) {
        wr[k] = *reinterpret_cast<const float4*>(&w1r[k * 128 + lane * 4]);
        wn[k] = *reinterpret_cast<const float4*>(&w1n[k * 128 + lane * 4]);
    }
    float4 bv = *reinterpret_cast<const float4*>(&b1[lane * 4]);

    int deg = g_deg[node];
    int off = g_off[node];

    float a0 = 0.f, a1 = 0.f, a2 = 0.f, a3 = 0.f, a4 = 0.f, a5 = 0.f;
    for (int i = lane; i < deg; i += 32) {
        int s = g_elist[off + i];
        const float2* xr = reinterpret_cast<const float2*>(x + s * 6);
        float2 v0 = xr[0], v1 = xr[1], v2 = xr[2];
        a0 += v0.x; a1 += v0.y; a2 += v1.x; a3 += v1.y; a4 += v2.x; a5 += v2.y;
    }
#pragma unroll
    for (int ofs = 16; ofs > 0; ofs >>= 1) {
        a0 += __shfl_xor_sync(0xffffffffu, a0, ofs);
        a1 += __shfl_xor_sync(0xffffffffu, a1, ofs);
        a2 += __shfl_xor_sync(0xffffffffu, a2, ofs);
        a3 += __shfl_xor_sync(0xffffffffu, a3, ofs);
        a4 += __shfl_xor_sync(0xffffffffu, a4, ofs);
        a5 += __shfl_xor_sync(0xffffffffu, a5, ofs);
    }
    float inv = 1.0f / fmaxf((float)deg, 1.0f);
    float m[6] = {a0 * inv, a1 * inv, a2 * inv, a3 * inv, a4 * inv, a5 * inv};

    const float2* xr = reinterpret_cast<const float2*>(x + node * 6);
    float2 x0 = xr[0], x1 = xr[1], x2 = xr[2];
    float xv[6] = {x0.x, x0.y, x1.x, x1.y, x2.x, x2.y};

    float4 h = bv;
#pragma unroll
    for (int k = 0; k < 6; k++) {
        h.x += xv[k] * wr[k].x + m[k] * wn[k].x;
        h.y += xv[k] * wr[k].y + m[k] * wn[k].y;
        h.z += xv[k] * wr[k].z + m[k] * wn[k].z;
        h.w += xv[k] * wr[k].w + m[k] * wn[k].w;
    }
    h.x = fmaxf(h.x, 0.f); h.y = fmaxf(h.y, 0.f);
    h.z = fmaxf(h.z, 0.f); h.w = fmaxf(h.w, 0.f);
    *reinterpret_cast<float4*>(&g_h1[(size_t)node * 128 + lane * 4]) = h;
}

// ============ k_gather2: mean of h1[srcs] -> g_agg2 (warp per node) ==========
__global__ void k_gather2() {
    int t = threadIdx.x;
    int lane = t & 31;
    int node = blockIdx.x * 8 + (t >> 5);
    int deg = g_deg[node];
    int off = g_off[node];

    float4 acc = make_float4(0.f, 0.f, 0.f, 0.f);
    int i = 0;
    for (; i + 4 <= deg; i += 4) {
        int s0 = g_elist[off + i + 0];
        int s1 = g_elist[off + i + 1];
        int s2 = g_elist[off + i + 2];
        int s3 = g_elist[off + i + 3];
        float4 v0 = *reinterpret_cast<const float4*>(&g_h1[(size_t)s0 * 128 + lane * 4]);
        float4 v1 = *reinterpret_cast<const float4*>(&g_h1[(size_t)s1 * 128 + lane * 4]);
        float4 v2 = *reinterpret_cast<const float4*>(&g_h1[(size_t)s2 * 128 + lane * 4]);
        float4 v3 = *reinterpret_cast<const float4*>(&g_h1[(size_t)s3 * 128 + lane * 4]);
        acc.x += v0.x + v1.x + v2.x + v3.x;
        acc.y += v0.y + v1.y + v2.y + v3.y;
        acc.z += v0.z + v1.z + v2.z + v3.z;
        acc.w += v0.w + v1.w + v2.w + v3.w;
    }
    for (; i < deg; i++) {
        int s = g_elist[off + i];
        float4 v = *reinterpret_cast<const float4*>(&g_h1[(size_t)s * 128 + lane * 4]);
        acc.x += v.x; acc.y += v.y; acc.z += v.z; acc.w += v.w;
    }
    float inv = 1.0f / fmaxf((float)deg, 1.0f);
    acc.x *= inv; acc.y *= inv; acc.z *= inv; acc.w *= inv;
    *reinterpret_cast<float4*>(&g_agg2[(size_t)node * 128 + lane * 4]) = acc;
}

// ================= k_h2_tf32: h2 = relu([h1|mean]@[W2r;W2n]+b2) ===============
#define H2_AS 0                       // 64*144   = 9216
#define H2_BS 9216                    // 64*1040  = 66560
#define H2_TOTAL 75776

__global__ __launch_bounds__(256, 2)
void k_h2_tf32(const float* __restrict__ w2r, const float* __restrict__ w2n,
               const float* __restrict__ b2) {
    extern __shared__ __align__(16) char smem[];
    uint32_t smem_base = smem_u32(smem);
    int t = threadIdx.x, wid = t >> 5, lane = t & 31;
    int wm = wid >> 1;
    int wn = wid & 1;
    int row0 = blockIdx.x * 64;
    int nbase = blockIdx.y * 64;

#pragma unroll 8
    for (int i = 0; i < 64; i++) {
        int idx = i * 256 + t;
        int k = idx >> 6, n = idx & 63;
        float w = (k < 128) ? w2r[k * 128 + nbase + n]
                            : w2n[(k - 128) * 128 + nbase + n];
        *(uint32_t*)(smem + H2_BS + (uint32_t)n * 1040 + (uint32_t)k * 4) = cvt_tf32(w);
    }

    int arow_st = t >> 2;
    int akg = (t & 3) * 8;
    int grow_st = row0 + arow_st;
    bool valid = grow_st < N_NODES;

    int arow = lane & 15;
    uint32_t acolb = (lane & 16) ? 16u : 0u;
    int b_nrow = ((lane >> 4) << 3) + (lane & 7);
    uint32_t b_kb = ((lane >> 3) & 1) ? 16u : 0u;

    float acc[4][4] = {};

#pragma unroll 1
    for (int kc = 0; kc < 8; kc++) {
        {
            float v[8] = {0, 0, 0, 0, 0, 0, 0, 0};
            if (valid) {
                const float* src = (kc < 4)
                    ? &g_h1[(size_t)grow_st * 128 + kc * 32 + akg]
                    : &g_agg2[(size_t)grow_st * 128 + (kc - 4) * 32 + akg];
                float4 v0 = *reinterpret_cast<const float4*>(src);
                float4 v1 = *reinterpret_cast<const float4*>(src + 4);
                v[0] = v0.x; v[1] = v0.y; v[2] = v0.z; v[3] = v0.w;
                v[4] = v1.x; v[5] = v1.y; v[6] = v1.z; v[7] = v1.w;
            }
            uint4 t0, t1;
            t0.x = cvt_tf32(v[0]); t0.y = cvt_tf32(v[1]);
            t0.z = cvt_tf32(v[2]); t0.w = cvt_tf32(v[3]);
            t1.x = cvt_tf32(v[4]); t1.y = cvt_tf32(v[5]);
            t1.z = cvt_tf32(v[6]); t1.w = cvt_tf32(v[7]);
            char* dst = smem + H2_AS + (uint32_t)arow_st * 144 + (uint32_t)akg * 4;
            *(uint4*)(dst) = t0;
            *(uint4*)(dst + 16) = t1;
        }
        __syncthreads();

#pragma unroll
        for (int ks = 0; ks < 4; ks++) {
            uint32_t a[4];
            ldsm4(a, smem_base + H2_AS + (uint32_t)(wm * 16 + arow) * 144
                     + acolb + (uint32_t)ks * 32);
            uint32_t b01[4], b23[4];
            uint32_t boff = (uint32_t)(wn * 32 + b_nrow) * 1040 + b_kb
                          + (uint32_t)(kc * 32 + ks * 8) * 4;
            ldsm4(b01, smem_base + H2_BS + boff);
            ldsm4(b23, smem_base + H2_BS + boff + 16 * 1040);
            uint32_t* bf[4] = {b01, b01 + 2, b23, b23 + 2};
#pragma unroll
            for (int nn = 0; nn < 4; nn++) mma_tf32(acc[nn], a, bf[nn]);
        }
        __syncthreads();
    }

    int erow = row0 + wm * 16 + (lane >> 2);
    int ecol = nbase + wn * 32 + (lane & 3) * 2;
#pragma unroll
    for (int nn = 0; nn < 4; nn++) {
        int c = ecol + nn * 8;
        float b0 = b2[c], b1 = b2[c + 1];
        if (erow < N_NODES) {
            float2 o = make_float2(fmaxf(acc[nn][0] + b0, 0.f),
                                   fmaxf(acc[nn][1] + b1, 0.f));
            *reinterpret_cast<float2*>(&g_h2[(size_t)erow * 128 + c]) = o;
        }
        if (erow + 8 < N_NODES) {
            float2 o = make_float2(fmaxf(acc[nn][2] + b0, 0.f),
                                   fmaxf(acc[nn][3] + b1, 0.f));
            *reinterpret_cast<float2*>(&g_h2[(size_t)(erow + 8) * 128 + c]) = o;
        }
    }
}

// ================= k_pq_tf32: p = h2@Wa (fp16 out), q = h2@Wb (fp32) ==========
#define PQ_AS 0
#define PQ_BS 9216
#define PQ_TOTAL 43008

__global__ __launch_bounds__(256, 2)
void k_pq_tf32(const float* __restrict__ we1) {
    extern __shared__ __align__(16) char smem[];
    uint32_t smem_base = smem_u32(smem);
    int t = threadIdx.x, wid = t >> 5, lane = t & 31;
    int wm = wid >> 1;
    int wn = wid & 1;
    int row0 = blockIdx.x * 64;
    int qtr = blockIdx.y;
    int nbase = (qtr & 1) * 64;
    int krow0 = (qtr < 2) ? 0 : 128;

#pragma unroll 8
    for (int i = 0; i < 32; i++) {
        int idx = i * 256 + t;
        int k = idx >> 6, n = idx & 63;
        float w = we1[(krow0 + k) * 128 + nbase + n];
        *(uint32_t*)(smem + PQ_BS + (uint32_t)n * 528 + (uint32_t)k * 4) = cvt_tf32(w);
    }

    int arow_st = t >> 2;
    int akg = (t & 3) * 8;
    int grow_st = row0 + arow_st;
    bool valid = grow_st < N_NODES;

    int arow = lane & 15;
    uint32_t acolb = (lane & 16) ? 16u : 0u;
    int b_nrow = ((lane >> 4) << 3) + (lane & 7);
    uint32_t b_kb = ((lane >> 3) & 1) ? 16u : 0u;

    float acc[4][4] = {};

#pragma unroll 1
    for (int kc = 0; kc < 4; kc++) {
        {
            float v[8] = {0, 0, 0, 0, 0, 0, 0, 0};
            if (valid) {
                const float* src = &g_h2[(size_t)grow_st * 128 + kc * 32 + akg];
                float4 v0 = *reinterpret_cast<const float4*>(src);
                float4 v1 = *reinterpret_cast<const float4*>(src + 4);
                v[0] = v0.x; v[1] = v0.y; v[2] = v0.z; v[3] = v0.w;
                v[4] = v1.x; v[5] = v1.y; v[6] = v1.z; v[7] = v1.w;
            }
            uint4 t0, t1;
            t0.x = cvt_tf32(v[0]); t0.y = cvt_tf32(v[1]);
            t0.z = cvt_tf32(v[2]); t0.w = cvt_tf32(v[3]);
            t1.x = cvt_tf32(v[4]); t1.y = cvt_tf32(v[5]);
            t1.z = cvt_tf32(v[6]); t1.w = cvt_tf32(v[7]);
            char* dst = smem + PQ_AS + (uint32_t)arow_st * 144 + (uint32_t)akg * 4;
            *(uint4*)(dst) = t0;
            *(uint4*)(dst + 16) = t1;
        }
        __syncthreads();

#pragma unroll
        for (int ks = 0; ks < 4; ks++) {
            uint32_t a[4];
            ldsm4(a, smem_base + PQ_AS + (uint32_t)(wm * 16 + arow) * 144
                     + acolb + (uint32_t)ks * 32);
            uint32_t b01[4], b23[4];
            uint32_t boff = (uint32_t)(wn * 32 + b_nrow) * 528 + b_kb
                          + (uint32_t)(kc * 32 + ks * 8) * 4;
            ldsm4(b01, smem_base + PQ_BS + boff);
            ldsm4(b23, smem_base + PQ_BS + boff + 16 * 528);
            uint32_t* bf[4] = {b01, b01 + 2, b23, b23 + 2};
#pragma unroll
            for (int nn = 0; nn < 4; nn++) mma_tf32(acc[nn], a, bf[nn]);
        }
        __syncthreads();
    }

    int erow = row0 + wm * 16 + (lane >> 2);
    int ecol = nbase + wn * 32 + (lane & 3) * 2;
    if (qtr < 2) {
#pragma unroll
        for (int nn = 0; nn < 4; nn++) {
            int c = ecol + nn * 8;
            if (erow < N_NODES)
                *reinterpret_cast<__half2*>(&g_p[(size_t)erow * 128 + c]) =
                    __floats2half2_rn(acc[nn][0], acc[nn][1]);
            if (erow + 8 < N_NODES)
                *reinterpret_cast<__half2*>(&g_p[(size_t)(erow + 8) * 128 + c]) =
                    __floats2half2_rn(acc[nn][2], acc[nn][3]);
        }
    } else {
#pragma unroll
        for (int nn = 0; nn < 4; nn++) {
            int c = ecol + nn * 8;
            if (erow < N_NODES)
                *reinterpret_cast<float2*>(&g_q[(size_t)erow * 128 + c]) =
                    make_float2(acc[nn][0], acc[nn][1]);
            if (erow + 8 < N_NODES)
                *reinterpret_cast<float2*>(&g_q[(size_t)(erow + 8) * 128 + c]) =
                    make_float2(acc[nn][2], acc[nn][3]);
        }
    }
}

// ========== edge MLP via tf32 mma, CSR order, fp16 p gather ===================
#define SM_A      0
#define SM_B      67584
#define SM_PA     101376
#define SM_PB     101888
#define SM_B2S    102400
#define SM_W3S    102656
#define SM_SRC    102912              // int[2][128]
#define SM_DST    103936              // int[2][128]
#define SM_EID    104960              // int[2][128]
#define SM_EAS    105984              // float[2][512]
#define SM_EDGE_TOTAL 110080

#define N_TILES (N_EDGES / 128)
#define EDGE_GRID 296

__global__ __launch_bounds__(256, 2)
void k_edge_tf32(const float* __restrict__ ea,
                 const float* __restrict__ we1, const float* __restrict__ be1,
                 const float* __restrict__ we2, const float* __restrict__ be2,
                 const float* __restrict__ we3, const float* __restrict__ be3,
                 float* __restrict__ out) {
    extern __shared__ __align__(16) char smem[];
    uint32_t smem_base = smem_u32(smem);
    int t = threadIdx.x;
    int wid = t >> 5, lane = t & 31;
    int wm = wid >> 1;
    int wn = wid & 1;

    float* pa  = (float*)(smem + SM_PA);
    float* pb  = (float*)(smem + SM_PB);
    float* b2s = (float*)(smem + SM_B2S);
    float* w3s = (float*)(smem + SM_W3S);
    int*   srcs = (int*)(smem + SM_SRC);
    int*   dsts = (int*)(smem + SM_DST);
    int*   eids = (int*)(smem + SM_EID);
    float* eas  = (float*)(smem + SM_EAS);

    if (t < 64) { b2s[t] = be2[t]; w3s[t] = we3[t]; }

    int kq = lane * 4;
    float4 b1v = *reinterpret_cast<const float4*>(&be1[kq]);
    float4 wc0 = *reinterpret_cast<const float4*>(&we1[256 * 128 + kq]);
    float4 wc1 = *reinterpret_cast<const float4*>(&we1[257 * 128 + kq]);
    float4 wc2 = *reinterpret_cast<const float4*>(&we1[258 * 128 + kq]);
    float4 wc3 = *reinterpret_cast<const float4*>(&we1[259 * 128 + kq]);

    for (int idx = t; idx < 64 * 128; idx += 256) {
        int n = idx >> 7, k = idx & 127;
        uint32_t w = cvt_tf32(we2[k * 64 + n]);
        *(uint32_t*)(smem + SM_B + (uint32_t)n * 528 + (uint32_t)k * 4) = w;
    }
    float be3v = be3[0];

    int arow = lane & 15;
    uint32_t acolb = (lane & 16) ? 16u : 0u;
    int b_nrow = wn * 32 + ((lane >> 4) << 3) + (lane & 7);
    uint32_t b_kb = ((lane >> 3) & 1) ? 16u : 0u;
    uint32_t b_base = (uint32_t)b_nrow * 528 + b_kb;

    int tile = blockIdx.x;
    {
        int e0 = tile * 128;
        if (t < 128) {
            srcs[t] = g_elist[e0 + t];
            int eid = g_eidl[e0 + t];
            eids[t] = eid;
            *reinterpret_cast<float4*>(&eas[t * 4]) =
                *reinterpret_cast<const float4*>(&ea[(size_t)eid * 4]);
        } else {
            dsts[t - 128] = g_dlist[e0 + (t - 128)];
        }
    }
    __syncthreads();

    int buf = 0;
    for (; tile < N_TILES; tile += EDGE_GRID) {
        int* sb = srcs + buf * 128;
        int* db = dsts + buf * 128;
        int* eb_id = eids + buf * 128;
        float* eb = eas + buf * 512;

        // ---- gather (p fp16, q fp32) + e1 + cvt.tf32 into smem A ----
#pragma unroll 4
        for (int i = 0; i < 16; i++) {
            int edge = i * 8 + wid;
            int s = sb[edge], d = db[edge];
            uint2 pu = *reinterpret_cast<const uint2*>(&g_p[(size_t)s * 128 + kq]);
            float2 p01 = __half22float2(*reinterpret_cast<__half2*>(&pu.x));
            float2 p23 = __half22float2(*reinterpret_cast<__half2*>(&pu.y));
            float4 qv = *reinterpret_cast<const float4*>(&g_q[(size_t)d * 128 + kq]);
            float4 e4 = *reinterpret_cast<const float4*>(&eb[edge * 4]);
            float v[4];
            v[0] = p01.x + qv.x + b1v.x + e4.x * wc0.x + e4.y * wc1.x + e4.z * wc2.x + e4.w * wc3.x;
            v[1] = p01.y + qv.y + b1v.y + e4.x * wc0.y + e4.y * wc1.y + e4.z * wc2.y + e4.w * wc3.y;
            v[2] = p23.x + qv.z + b1v.z + e4.x * wc0.z + e4.y * wc1.z + e4.z * wc2.z + e4.w * wc3.z;
            v[3] = p23.y + qv.w + b1v.w + e4.x * wc0.w + e4.y * wc1.w + e4.z * wc2.w + e4.w * wc3.w;
            uint4 tv;
            tv.x = cvt_tf32(fmaxf(v[0], 0.f));
            tv.y = cvt_tf32(fmaxf(v[1], 0.f));
            tv.z = cvt_tf32(fmaxf(v[2], 0.f));
            tv.w = cvt_tf32(fmaxf(v[3], 0.f));
            *(uint4*)(smem + SM_A + (uint32_t)edge * 528 + (uint32_t)kq * 4) = tv;
        }

        // ---- stage next tile into other buffer ----
        int nxt = tile + EDGE_GRID;
        if (nxt < N_TILES) {
            int e0n = nxt * 128;
            int* sn = srcs + (buf ^ 1) * 128;
            int* dn = dsts + (buf ^ 1) * 128;
            int* en_id = eids + (buf ^ 1) * 128;
            float* en = eas + (buf ^ 1) * 512;
            if (t < 128) {
                sn[t] = g_elist[e0n + t];
                int eid = g_eidl[e0n + t];
                en_id[t] = eid;
                *reinterpret_cast<float4*>(&en[t * 4]) =
                    *reinterpret_cast<const float4*>(&ea[(size_t)eid * 4]);
            } else {
                dn[t - 128] = g_dlist[e0n + (t - 128)];
            }
        }
        __syncthreads();

        float acc[2][4][4];
#pragma unroll
        for (int mi = 0; mi < 2; mi++)
#pragma unroll
            for (int nn = 0; nn < 4; nn++)
#pragma unroll
                for (int r = 0; r < 4; r++) acc[mi][nn][r] = 0.f;

#pragma unroll
        for (int kk = 0; kk < 16; kk++) {
            uint32_t a0[4], a1[4];
            uint32_t aoff = (uint32_t)(wm * 32 + arow) * 528 + acolb + (uint32_t)kk * 32;
            ldsm4(a0, smem_base + SM_A + aoff);
            ldsm4(a1, smem_base + SM_A + aoff + 16 * 528);

            uint32_t b01[4], b23[4];
            uint32_t boff = b_base + (uint32_t)kk * 32;
            ldsm4(b01, smem_base + SM_B + boff);
            ldsm4(b23, smem_base + SM_B + boff + 16 * 528);
            uint32_t* bf[4] = {b01, b01 + 2, b23, b23 + 2};

#pragma unroll
            for (int nn = 0; nn < 4; nn++) {
                mma_tf32(acc[0][nn], a0, bf[nn]);
                mma_tf32(acc[1][nn], a1, bf[nn]);
            }
        }

        float part[2][2] = {{0.f, 0.f}, {0.f, 0.f}};
#pragma unroll
        for (int mi = 0; mi < 2; mi++) {
#pragma unroll
            for (int nn = 0; nn < 4; nn++) {
                int c0 = wn * 32 + nn * 8 + (lane & 3) * 2;
                float w30 = w3s[c0], w31 = w3s[c0 + 1];
                float bb0 = b2s[c0], bb1 = b2s[c0 + 1];
                part[mi][0] += fmaxf(acc[mi][nn][0] + bb0, 0.f) * w30
                             + fmaxf(acc[mi][nn][1] + bb1, 0.f) * w31;
                part[mi][1] += fmaxf(acc[mi][nn][2] + bb0, 0.f) * w30
                             + fmaxf(acc[mi][nn][3] + bb1, 0.f) * w31;
            }
        }
#pragma unroll
        for (int mi = 0; mi < 2; mi++) {
#pragma unroll
            for (int g = 0; g < 2; g++) {
                part[mi][g] += __shfl_xor_sync(0xffffffffu, part[mi][g], 1);
                part[mi][g] += __shfl_xor_sync(0xffffffffu, part[mi][g], 2);
            }
        }
        if ((lane & 3) == 0) {
            float* pw = wn ? pb : pa;
            int r0 = wm * 32 + (lane >> 2);
            pw[r0]      = part[0][0];
            pw[r0 + 8]  = part[0][1];
            pw[r0 + 16] = part[1][0];
            pw[r0 + 24] = part[1][1];
        }
        __syncthreads();
        if (t < 128) out[eb_id[t]] = pa[t] + pb[t] + be3v;
        buf ^= 1;
    }
}

// ---------------- launch ----------------
extern "C" void kernel_launch(void* const* d_in, const int* in_sizes, int n_in,
                              void* d_out, int out_size) {
    const float* x   = (const float*)d_in[0];
    const int*   ei  = (const int*)d_in[1];
    const float* ea  = (const float*)d_in[2];
    const float* w1r = (const float*)d_in[3];
    const float* w1n = (const float*)d_in[4];
    const float* b1  = (const float*)d_in[5];
    const float* w2r = (const float*)d_in[6];
    const float* w2n = (const float*)d_in[7];
    const float* b2  = (const float*)d_in[8];
    const float* we1 = (const float*)d_in[9];
    const float* be1 = (const float*)d_in[10];
    const float* we2 = (const float*)d_in[11];
    const float* be2 = (const float*)d_in[12];
    const float* we3 = (const float*)d_in[13];
    const float* be3 = (const float*)d_in[14];
    float* out = (float*)d_out;

    cudaFuncSetAttribute(k_h2_tf32, cudaFuncAttributeMaxDynamicSharedMemorySize,
                         H2_TOTAL);
    cudaFuncSetAttribute(k_pq_tf32, cudaFuncAttributeMaxDynamicSharedMemorySize,
                         PQ_TOTAL);
    cudaFuncSetAttribute(k_edge_tf32, cudaFuncAttributeMaxDynamicSharedMemorySize,
                         SM_EDGE_TOTAL);

    // CSR build
    k_zero_deg<<<SCAN_B, 1024>>>();
    k_hist<<<N_EDGES / 256, 256>>>(ei);
    k_scan1<<<SCAN_B, 1024>>>();
    k_scan2<<<1, 128>>>();
    k_scan3<<<SCAN_B, 1024>>>();
    k_scatter<<<N_EDGES / 256, 256>>>(ei);
    // node pipeline
    k_h1g<<<N_NODES / 8, 256>>>(x, w1r, w1n, b1);
    k_gather2<<<N_NODES / 8, 256>>>();
    k_h2_tf32<<<dim3((N_NODES + 63) / 64, 2), 256, H2_TOTAL>>>(w2r, w2n, b2);
    k_pq_tf32<<<dim3((N_NODES + 63) / 64, 4), 256, PQ_TOTAL>>>(we1);
    // edge pipeline
    k_edge_tf32<<<EDGE_GRID, 256, SM_EDGE_TOTAL>>>(ea, we1, be1, we2, be2, we3, be3, out);
}

// round 17
// speedup vs baseline: 1.1364x; 1.0321x over previous
#include <cuda_runtime.h>
#include <cuda_bf16.h>
#include <cuda_fp16.h>
#include <cstdint>

#define N_NODES 100000
#define N_EDGES 1600000
#define HID 128
#define SCAN_B 98                    // ceil(100000/1024)

// ---------------- scratch (device globals; no allocation) ----------------
__device__ int   g_deg [N_NODES];
__device__ int   g_off [N_NODES];
__device__ int   g_cur [N_NODES];
__device__ int   g_bsum[128];
__device__ int   g_elist[N_EDGES];   // src ids grouped by dst
__device__ int   g_dlist[N_EDGES];   // dst id per CSR position
__device__ int   g_eidl [N_EDGES];   // original edge id per CSR position
__device__ __half g_h1 [N_NODES * HID];   // fp16 (gathered 819MB -> 410MB)
__device__ float g_agg2[N_NODES * HID];   // mean of h1 over in-edges (fp32)
__device__ float g_h2  [N_NODES * HID];
__device__ __half g_p  [N_NODES * HID];   // h2 @ W_e1[0:128], fp16
__device__ float g_q   [N_NODES * HID];   // h2 @ W_e1[128:256], fp32

// ---------------- warp MMA helpers (baseline PTX) ----------------
__device__ __forceinline__ uint32_t smem_u32(const void* p) {
    uint32_t a;
    asm("{ .reg .u64 t; cvta.to.shared.u64 t, %1; cvt.u32.u64 %0, t; }" : "=r"(a) : "l"(p));
    return a;
}
__device__ __forceinline__ void mma_tf32(float* d, const uint32_t* a, const uint32_t* b) {
    asm volatile(
        "mma.sync.aligned.m16n8k8.row.col.f32.tf32.tf32.f32 "
        "{%0,%1,%2,%3}, {%4,%5,%6,%7}, {%8,%9}, {%0,%1,%2,%3};"
        : "+f"(d[0]), "+f"(d[1]), "+f"(d[2]), "+f"(d[3])
        : "r"(a[0]), "r"(a[1]), "r"(a[2]), "r"(a[3]), "r"(b[0]), "r"(b[1]));
}
__device__ __forceinline__ void ldsm4(uint32_t* r, uint32_t addr) {
    asm volatile("ldmatrix.sync.aligned.m8n8.x4.shared.b16 {%0,%1,%2,%3}, [%4];"
                 : "=r"(r[0]), "=r"(r[1]), "=r"(r[2]), "=r"(r[3]) : "r"(addr));
}
__device__ __forceinline__ uint32_t cvt_tf32(float x) {
    uint32_t u;
    asm("cvt.rna.tf32.f32 %0, %1;" : "=r"(u) : "f"(x));
    return u;
}

// ================== CSR build ==================
__global__ void k_zero_deg() {
    int i = blockIdx.x * 1024 + threadIdx.x;
    if (i < N_NODES) g_deg[i] = 0;
}
__global__ void k_hist(const int* __restrict__ ei) {
    int e = blockIdx.x * 256 + threadIdx.x;
    atomicAdd(&g_deg[ei[N_EDGES + e]], 1);
}
__global__ void k_scan1() {
    __shared__ int sh[1024];
    int tid = threadIdx.x;
    int i = blockIdx.x * 1024 + tid;
    int v = (i < N_NODES) ? g_deg[i] : 0;
    sh[tid] = v;
    __syncthreads();
#pragma unroll
    for (int ofs = 1; ofs < 1024; ofs <<= 1) {
        int o = (tid >= ofs) ? sh[tid - ofs] : 0;
        __syncthreads();
        sh[tid] += o;
        __syncthreads();
    }
    if (i < N_NODES) g_off[i] = sh[tid] - v;
    if (tid == 1023) g_bsum[blockIdx.x] = sh[1023];
}
__global__ void k_scan2() {
    __shared__ int sh[128];
    int t = threadIdx.x;
    int v = (t < SCAN_B) ? g_bsum[t] : 0;
    sh[t] = v;
    __syncthreads();
#pragma unroll
    for (int ofs = 1; ofs < 128; ofs <<= 1) {
        int o = (t >= ofs) ? sh[t - ofs] : 0;
        __syncthreads();
        sh[t] += o;
        __syncthreads();
    }
    if (t < SCAN_B) g_bsum[t] = sh[t] - v;
}
__global__ void k_scan3() {
    int i = blockIdx.x * 1024 + threadIdx.x;
    if (i < N_NODES) {
        int o = g_off[i] + g_bsum[blockIdx.x];
        g_off[i] = o;
        g_cur[i] = o;
    }
}
__global__ void k_scatter(const int* __restrict__ ei) {
    int e = blockIdx.x * 256 + threadIdx.x;
    int s = ei[e];
    int d = ei[N_EDGES + e];
    int pos = atomicAdd(&g_cur[d], 1);
    g_elist[pos] = s;
    g_dlist[pos] = d;
    g_eidl[pos] = e;
}

// ============ k_h1g: fused x-mean gather + h1 MLP (warp per node) ============
__global__ void k_h1g(const float* __restrict__ x,
                      const float* __restrict__ w1r, const float* __restrict__ w1n,
                      const float* __restrict__ b1) {
    int t = threadIdx.x;
    int lane = t & 31;
    int node = blockIdx.x * 8 + (t >> 5);

    float4 wr[6], wn[6];
#pragma unroll
    for (int k = 0; k < 6; k++) {
        wr[k] = *reinterpret_cast<const float4*>(&w1r[k * 128 + lane * 4]);
        wn[k] = *reinterpret_cast<const float4*>(&w1n[k * 128 + lane * 4]);
    }
    float4 bv = *reinterpret_cast<const float4*>(&b1[lane * 4]);

    int deg = g_deg[node];
    int off = g_off[node];

    float a0 = 0.f, a1 = 0.f, a2 = 0.f, a3 = 0.f, a4 = 0.f, a5 = 0.f;
    for (int i = lane; i < deg; i += 32) {
        int s = g_elist[off + i];
        const float2* xr = reinterpret_cast<const float2*>(x + s * 6);
        float2 v0 = xr[0], v1 = xr[1], v2 = xr[2];
        a0 += v0.x; a1 += v0.y; a2 += v1.x; a3 += v1.y; a4 += v2.x; a5 += v2.y;
    }
#pragma unroll
    for (int ofs = 16; ofs > 0; ofs >>= 1) {
        a0 += __shfl_xor_sync(0xffffffffu, a0, ofs);
        a1 += __shfl_xor_sync(0xffffffffu, a1, ofs);
        a2 += __shfl_xor_sync(0xffffffffu, a2, ofs);
        a3 += __shfl_xor_sync(0xffffffffu, a3, ofs);
        a4 += __shfl_xor_sync(0xffffffffu, a4, ofs);
        a5 += __shfl_xor_sync(0xffffffffu, a5, ofs);
    }
    float inv = 1.0f / fmaxf((float)deg, 1.0f);
    float m[6] = {a0 * inv, a1 * inv, a2 * inv, a3 * inv, a4 * inv, a5 * inv};

    const float2* xr = reinterpret_cast<const float2*>(x + node * 6);
    float2 x0 = xr[0], x1 = xr[1], x2 = xr[2];
    float xv[6] = {x0.x, x0.y, x1.x, x1.y, x2.x, x2.y};

    float4 h = bv;
#pragma unroll
    for (int k = 0; k < 6; k++) {
        h.x += xv[k] * wr[k].x + m[k] * wn[k].x;
        h.y += xv[k] * wr[k].y + m[k] * wn[k].y;
        h.z += xv[k] * wr[k].z + m[k] * wn[k].z;
        h.w += xv[k] * wr[k].w + m[k] * wn[k].w;
    }
    h.x = fmaxf(h.x, 0.f); h.y = fmaxf(h.y, 0.f);
    h.z = fmaxf(h.z, 0.f); h.w = fmaxf(h.w, 0.f);
    uint2 hp;
    *reinterpret_cast<__half2*>(&hp.x) = __floats2half2_rn(h.x, h.y);
    *reinterpret_cast<__half2*>(&hp.y) = __floats2half2_rn(h.z, h.w);
    *reinterpret_cast<uint2*>(&g_h1[(size_t)node * 128 + lane * 4]) = hp;
}

// ============ k_gather2: mean of fp16 h1[srcs] -> g_agg2 (warp per node) =====
__global__ void k_gather2() {
    int t = threadIdx.x;
    int lane = t & 31;
    int node = blockIdx.x * 8 + (t >> 5);
    int deg = g_deg[node];
    int off = g_off[node];

    float4 acc = make_float4(0.f, 0.f, 0.f, 0.f);
    int i = 0;
    for (; i + 4 <= deg; i += 4) {
        int s0 = g_elist[off + i + 0];
        int s1 = g_elist[off + i + 1];
        int s2 = g_elist[off + i + 2];
        int s3 = g_elist[off + i + 3];
        uint2 u0 = *reinterpret_cast<const uint2*>(&g_h1[(size_t)s0 * 128 + lane * 4]);
        uint2 u1 = *reinterpret_cast<const uint2*>(&g_h1[(size_t)s1 * 128 + lane * 4]);
        uint2 u2 = *reinterpret_cast<const uint2*>(&g_h1[(size_t)s2 * 128 + lane * 4]);
        uint2 u3 = *reinterpret_cast<const uint2*>(&g_h1[(size_t)s3 * 128 + lane * 4]);
#pragma unroll
        for (int j = 0; j < 4; j++) {
            uint2 u = j == 0 ? u0 : (j == 1 ? u1 : (j == 2 ? u2 : u3));
            float2 lo = __half22float2(*reinterpret_cast<__half2*>(&u.x));
            float2 hi = __half22float2(*reinterpret_cast<__half2*>(&u.y));
            acc.x += lo.x; acc.y += lo.y; acc.z += hi.x; acc.w += hi.y;
        }
    }
    for (; i < deg; i++) {
        int s = g_elist[off + i];
        uint2 u = *reinterpret_cast<const uint2*>(&g_h1[(size_t)s * 128 + lane * 4]);
        float2 lo = __half22float2(*reinterpret_cast<__half2*>(&u.x));
        float2 hi = __half22float2(*reinterpret_cast<__half2*>(&u.y));
        acc.x += lo.x; acc.y += lo.y; acc.z += hi.x; acc.w += hi.y;
    }
    float inv = 1.0f / fmaxf((float)deg, 1.0f);
    acc.x *= inv; acc.y *= inv; acc.z *= inv; acc.w *= inv;
    *reinterpret_cast<float4*>(&g_agg2[(size_t)node * 128 + lane * 4]) = acc;
}

// ================= k_h2_tf32: h2 = relu([h1|mean]@[W2r;W2n]+b2) ===============
#define H2_AS 0                       // 64*144   = 9216
#define H2_BS 9216                    // 64*1040  = 66560
#define H2_TOTAL 75776

__global__ __launch_bounds__(256, 2)
void k_h2_tf32(const float* __restrict__ w2r, const float* __restrict__ w2n,
               const float* __restrict__ b2) {
    extern __shared__ __align__(16) char smem[];
    uint32_t smem_base = smem_u32(smem);
    int t = threadIdx.x, wid = t >> 5, lane = t & 31;
    int wm = wid >> 1;
    int wn = wid & 1;
    int row0 = blockIdx.x * 64;
    int nbase = blockIdx.y * 64;

#pragma unroll 8
    for (int i = 0; i < 64; i++) {
        int idx = i * 256 + t;
        int k = idx >> 6, n = idx & 63;
        float w = (k < 128) ? w2r[k * 128 + nbase + n]
                            : w2n[(k - 128) * 128 + nbase + n];
        *(uint32_t*)(smem + H2_BS + (uint32_t)n * 1040 + (uint32_t)k * 4) = cvt_tf32(w);
    }

    int arow_st = t >> 2;
    int akg = (t & 3) * 8;
    int grow_st = row0 + arow_st;
    bool valid = grow_st < N_NODES;

    int arow = lane & 15;
    uint32_t acolb = (lane & 16) ? 16u : 0u;
    int b_nrow = ((lane >> 4) << 3) + (lane & 7);
    uint32_t b_kb = ((lane >> 3) & 1) ? 16u : 0u;

    float acc[4][4] = {};

#pragma unroll 1
    for (int kc = 0; kc < 8; kc++) {
        {
            float v[8] = {0, 0, 0, 0, 0, 0, 0, 0};
            if (valid) {
                if (kc < 4) {
                    uint4 u = *reinterpret_cast<const uint4*>(
                        &g_h1[(size_t)grow_st * 128 + kc * 32 + akg]);
                    float2 f0 = __half22float2(*reinterpret_cast<__half2*>(&u.x));
                    float2 f1 = __half22float2(*reinterpret_cast<__half2*>(&u.y));
                    float2 f2 = __half22float2(*reinterpret_cast<__half2*>(&u.z));
                    float2 f3 = __half22float2(*reinterpret_cast<__half2*>(&u.w));
                    v[0] = f0.x; v[1] = f0.y; v[2] = f1.x; v[3] = f1.y;
                    v[4] = f2.x; v[5] = f2.y; v[6] = f3.x; v[7] = f3.y;
                } else {
                    const float* src = &g_agg2[(size_t)grow_st * 128 + (kc - 4) * 32 + akg];
                    float4 v0 = *reinterpret_cast<const float4*>(src);
                    float4 v1 = *reinterpret_cast<const float4*>(src + 4);
                    v[0] = v0.x; v[1] = v0.y; v[2] = v0.z; v[3] = v0.w;
                    v[4] = v1.x; v[5] = v1.y; v[6] = v1.z; v[7] = v1.w;
                }
            }
            uint4 t0, t1;
            t0.x = cvt_tf32(v[0]); t0.y = cvt_tf32(v[1]);
            t0.z = cvt_tf32(v[2]); t0.w = cvt_tf32(v[3]);
            t1.x = cvt_tf32(v[4]); t1.y = cvt_tf32(v[5]);
            t1.z = cvt_tf32(v[6]); t1.w = cvt_tf32(v[7]);
            char* dst = smem + H2_AS + (uint32_t)arow_st * 144 + (uint32_t)akg * 4;
            *(uint4*)(dst) = t0;
            *(uint4*)(dst + 16) = t1;
        }
        __syncthreads();

#pragma unroll
        for (int ks = 0; ks < 4; ks++) {
            uint32_t a[4];
            ldsm4(a, smem_base + H2_AS + (uint32_t)(wm * 16 + arow) * 144
                     + acolb + (uint32_t)ks * 32);
            uint32_t b01[4], b23[4];
            uint32_t boff = (uint32_t)(wn * 32 + b_nrow) * 1040 + b_kb
                          + (uint32_t)(kc * 32 + ks * 8) * 4;
            ldsm4(b01, smem_base + H2_BS + boff);
            ldsm4(b23, smem_base + H2_BS + boff + 16 * 1040);
            uint32_t* bf[4] = {b01, b01 + 2, b23, b23 + 2};
#pragma unroll
            for (int nn = 0; nn < 4; nn++) mma_tf32(acc[nn], a, bf[nn]);
        }
        __syncthreads();
    }

    int erow = row0 + wm * 16 + (lane >> 2);
    int ecol = nbase + wn * 32 + (lane & 3) * 2;
#pragma unroll
    for (int nn = 0; nn < 4; nn++) {
        int c = ecol + nn * 8;
        float b0 = b2[c], b1 = b2[c + 1];
        if (erow < N_NODES) {
            float2 o = make_float2(fmaxf(acc[nn][0] + b0, 0.f),
                                   fmaxf(acc[nn][1] + b1, 0.f));
            *reinterpret_cast<float2*>(&g_h2[(size_t)erow * 128 + c]) = o;
        }
        if (erow + 8 < N_NODES) {
            float2 o = make_float2(fmaxf(acc[nn][2] + b0, 0.f),
                                   fmaxf(acc[nn][3] + b1, 0.f));
            *reinterpret_cast<float2*>(&g_h2[(size_t)(erow + 8) * 128 + c]) = o;
        }
    }
}

// ================= k_pq_tf32: p = h2@Wa (fp16 out), q = h2@Wb (fp32) ==========
#define PQ_AS 0
#define PQ_BS 9216
#define PQ_TOTAL 43008

__global__ __launch_bounds__(256, 2)
void k_pq_tf32(const float* __restrict__ we1) {
    extern __shared__ __align__(16) char smem[];
    uint32_t smem_base = smem_u32(smem);
    int t = threadIdx.x, wid = t >> 5, lane = t & 31;
    int wm = wid >> 1;
    int wn = wid & 1;
    int row0 = blockIdx.x * 64;
    int qtr = blockIdx.y;
    int nbase = (qtr & 1) * 64;
    int krow0 = (qtr < 2) ? 0 : 128;

#pragma unroll 8
    for (int i = 0; i < 32; i++) {
        int idx = i * 256 + t;
        int k = idx >> 6, n = idx & 63;
        float w = we1[(krow0 + k) * 128 + nbase + n];
        *(uint32_t*)(smem + PQ_BS + (uint32_t)n * 528 + (uint32_t)k * 4) = cvt_tf32(w);
    }

    int arow_st = t >> 2;
    int akg = (t & 3) * 8;
    int grow_st = row0 + arow_st;
    bool valid = grow_st < N_NODES;

    int arow = lane & 15;
    uint32_t acolb = (lane & 16) ? 16u : 0u;
    int b_nrow = ((lane >> 4) << 3) + (lane & 7);
    uint32_t b_kb = ((lane >> 3) & 1) ? 16u : 0u;

    float acc[4][4] = {};

#pragma unroll 1
    for (int kc = 0; kc < 4; kc++) {
        {
            float v[8] = {0, 0, 0, 0, 0, 0, 0, 0};
            if (valid) {
                const float* src = &g_h2[(size_t)grow_st * 128 + kc * 32 + akg];
                float4 v0 = *reinterpret_cast<const float4*>(src);
                float4 v1 = *reinterpret_cast<const float4*>(src + 4);
                v[0] = v0.x; v[1] = v0.y; v[2] = v0.z; v[3] = v0.w;
                v[4] = v1.x; v[5] = v1.y; v[6] = v1.z; v[7] = v1.w;
            }
            uint4 t0, t1;
            t0.x = cvt_tf32(v[0]); t0.y = cvt_tf32(v[1]);
            t0.z = cvt_tf32(v[2]); t0.w = cvt_tf32(v[3]);
            t1.x = cvt_tf32(v[4]); t1.y = cvt_tf32(v[5]);
            t1.z = cvt_tf32(v[6]); t1.w = cvt_tf32(v[7]);
            char* dst = smem + PQ_AS + (uint32_t)arow_st * 144 + (uint32_t)akg * 4;
            *(uint4*)(dst) = t0;
            *(uint4*)(dst + 16) = t1;
        }
        __syncthreads();

#pragma unroll
        for (int ks = 0; ks < 4; ks++) {
            uint32_t a[4];
            ldsm4(a, smem_base + PQ_AS + (uint32_t)(wm * 16 + arow) * 144
                     + acolb + (uint32_t)ks * 32);
            uint32_t b01[4], b23[4];
            uint32_t boff = (uint32_t)(wn * 32 + b_nrow) * 528 + b_kb
                          + (uint32_t)(kc * 32 + ks * 8) * 4;
            ldsm4(b01, smem_base + PQ_BS + boff);
            ldsm4(b23, smem_base + PQ_BS + boff + 16 * 528);
            uint32_t* bf[4] = {b01, b01 + 2, b23, b23 + 2};
#pragma unroll
            for (int nn = 0; nn < 4; nn++) mma_tf32(acc[nn], a, bf[nn]);
        }
        __syncthreads();
    }

    int erow = row0 + wm * 16 + (lane >> 2);
    int ecol = nbase + wn * 32 + (lane & 3) * 2;
    if (qtr < 2) {
#pragma unroll
        for (int nn = 0; nn < 4; nn++) {
            int c = ecol + nn * 8;
            if (erow < N_NODES)
                *reinterpret_cast<__half2*>(&g_p[(size_t)erow * 128 + c]) =
                    __floats2half2_rn(acc[nn][0], acc[nn][1]);
            if (erow + 8 < N_NODES)
                *reinterpret_cast<__half2*>(&g_p[(size_t)(erow + 8) * 128 + c]) =
                    __floats2half2_rn(acc[nn][2], acc[nn][3]);
        }
    } else {
#pragma unroll
        for (int nn = 0; nn < 4; nn++) {
            int c = ecol + nn * 8;
            if (erow < N_NODES)
                *reinterpret_cast<float2*>(&g_q[(size_t)erow * 128 + c]) =
                    make_float2(acc[nn][0], acc[nn][1]);
            if (erow + 8 < N_NODES)
                *reinterpret_cast<float2*>(&g_q[(size_t)(erow + 8) * 128 + c]) =
                    make_float2(acc[nn][2], acc[nn][3]);
        }
    }
}

// ========== edge MLP via tf32 mma, CSR order, fp16 p gather ===================
#define SM_A      0
#define SM_B      67584
#define SM_PA     101376
#define SM_PB     101888
#define SM_B2S    102400
#define SM_W3S    102656
#define SM_SRC    102912              // int[2][128]
#define SM_DST    103936              // int[2][128]
#define SM_EID    104960              // int[2][128]
#define SM_EAS    105984              // float[2][512]
#define SM_EDGE_TOTAL 110080

#define N_TILES (N_EDGES / 128)
#define EDGE_GRID 296

__global__ __launch_bounds__(256, 2)
void k_edge_tf32(const float* __restrict__ ea,
                 const float* __restrict__ we1, const float* __restrict__ be1,
                 const float* __restrict__ we2, const float* __restrict__ be2,
                 const float* __restrict__ we3, const float* __restrict__ be3,
                 float* __restrict__ out) {
    extern __shared__ __align__(16) char smem[];
    uint32_t smem_base = smem_u32(smem);
    int t = threadIdx.x;
    int wid = t >> 5, lane = t & 31;
    int wm = wid >> 1;
    int wn = wid & 1;

    float* pa  = (float*)(smem + SM_PA);
    float* pb  = (float*)(smem + SM_PB);
    float* b2s = (float*)(smem + SM_B2S);
    float* w3s = (float*)(smem + SM_W3S);
    int*   srcs = (int*)(smem + SM_SRC);
    int*   dsts = (int*)(smem + SM_DST);
    int*   eids = (int*)(smem + SM_EID);
    float* eas  = (float*)(smem + SM_EAS);

    if (t < 64) { b2s[t] = be2[t]; w3s[t] = we3[t]; }

    int kq = lane * 4;
    float4 b1v = *reinterpret_cast<const float4*>(&be1[kq]);
    float4 wc0 = *reinterpret_cast<const float4*>(&we1[256 * 128 + kq]);
    float4 wc1 = *reinterpret_cast<const float4*>(&we1[257 * 128 + kq]);
    float4 wc2 = *reinterpret_cast<const float4*>(&we1[258 * 128 + kq]);
    float4 wc3 = *reinterpret_cast<const float4*>(&we1[259 * 128 + kq]);

    for (int idx = t; idx < 64 * 128; idx += 256) {
        int n = idx >> 7, k = idx & 127;
        uint32_t w = cvt_tf32(we2[k * 64 + n]);
        *(uint32_t*)(smem + SM_B + (uint32_t)n * 528 + (uint32_t)k * 4) = w;
    }
    float be3v = be3[0];

    int arow = lane & 15;
    uint32_t acolb = (lane & 16) ? 16u : 0u;
    int b_nrow = wn * 32 + ((lane >> 4) << 3) + (lane & 7);
    uint32_t b_kb = ((lane >> 3) & 1) ? 16u : 0u;
    uint32_t b_base = (uint32_t)b_nrow * 528 + b_kb;

    int tile = blockIdx.x;
    {
        int e0 = tile * 128;
        if (t < 128) {
            srcs[t] = g_elist[e0 + t];
            int eid = g_eidl[e0 + t];
            eids[t] = eid;
            *reinterpret_cast<float4*>(&eas[t * 4]) =
                *reinterpret_cast<const float4*>(&ea[(size_t)eid * 4]);
        } else {
            dsts[t - 128] = g_dlist[e0 + (t - 128)];
        }
    }
    __syncthreads();

    int buf = 0;
    for (; tile < N_TILES; tile += EDGE_GRID) {
        int* sb = srcs + buf * 128;
        int* db = dsts + buf * 128;
        int* eb_id = eids + buf * 128;
        float* eb = eas + buf * 512;

        // ---- gather (p fp16, q fp32) + e1 + cvt.tf32 into smem A ----
#pragma unroll 4
        for (int i = 0; i < 16; i++) {
            int edge = i * 8 + wid;
            int s = sb[edge], d = db[edge];
            uint2 pu = *reinterpret_cast<const uint2*>(&g_p[(size_t)s * 128 + kq]);
            float2 p01 = __half22float2(*reinterpret_cast<__half2*>(&pu.x));
            float2 p23 = __half22float2(*reinterpret_cast<__half2*>(&pu.y));
            float4 qv = *reinterpret_cast<const float4*>(&g_q[(size_t)d * 128 + kq]);
            float4 e4 = *reinterpret_cast<const float4*>(&eb[edge * 4]);
            float v[4];
            v[0] = p01.x + qv.x + b1v.x + e4.x * wc0.x + e4.y * wc1.x + e4.z * wc2.x + e4.w * wc3.x;
            v[1] = p01.y + qv.y + b1v.y + e4.x * wc0.y + e4.y * wc1.y + e4.z * wc2.y + e4.w * wc3.y;
            v[2] = p23.x + qv.z + b1v.z + e4.x * wc0.z + e4.y * wc1.z + e4.z * wc2.z + e4.w * wc3.z;
            v[3] = p23.y + qv.w + b1v.w + e4.x * wc0.w + e4.y * wc1.w + e4.z * wc2.w + e4.w * wc3.w;
            uint4 tv;
            tv.x = cvt_tf32(fmaxf(v[0], 0.f));
            tv.y = cvt_tf32(fmaxf(v[1], 0.f));
            tv.z = cvt_tf32(fmaxf(v[2], 0.f));
            tv.w = cvt_tf32(fmaxf(v[3], 0.f));
            *(uint4*)(smem + SM_A + (uint32_t)edge * 528 + (uint32_t)kq * 4) = tv;
        }

        // ---- stage next tile into other buffer ----
        int nxt = tile + EDGE_GRID;
        if (nxt < N_TILES) {
            int e0n = nxt * 128;
            int* sn = srcs + (buf ^ 1) * 128;
            int* dn = dsts + (buf ^ 1) * 128;
            int* en_id = eids + (buf ^ 1) * 128;
            float* en = eas + (buf ^ 1) * 512;
            if (t < 128) {
                sn[t] = g_elist[e0n + t];
                int eid = g_eidl[e0n + t];
                en_id[t] = eid;
                *reinterpret_cast<float4*>(&en[t * 4]) =
                    *reinterpret_cast<const float4*>(&ea[(size_t)eid * 4]);
            } else {
                dn[t - 128] = g_dlist[e0n + (t - 128)];
            }
        }
        __syncthreads();

        float acc[2][4][4];
#pragma unroll
        for (int mi = 0; mi < 2; mi++)
#pragma unroll
            for (int nn = 0; nn < 4; nn++)
#pragma unroll
                for (int r = 0; r < 4; r++) acc[mi][nn][r] = 0.f;

#pragma unroll
        for (int kk = 0; kk < 16; kk++) {
            uint32_t a0[4], a1[4];
            uint32_t aoff = (uint32_t)(wm * 32 + arow) * 528 + acolb + (uint32_t)kk * 32;
            ldsm4(a0, smem_base + SM_A + aoff);
            ldsm4(a1, smem_base + SM_A + aoff + 16 * 528);

            uint32_t b01[4], b23[4];
            uint32_t boff = b_base + (uint32_t)kk * 32;
            ldsm4(b01, smem_base + SM_B + boff);
            ldsm4(b23, smem_base + SM_B + boff + 16 * 528);
            uint32_t* bf[4] = {b01, b01 + 2, b23, b23 + 2};

#pragma unroll
            for (int nn = 0; nn < 4; nn++) {
                mma_tf32(acc[0][nn], a0, bf[nn]);
                mma_tf32(acc[1][nn], a1, bf[nn]);
            }
        }

        float part[2][2] = {{0.f, 0.f}, {0.f, 0.f}};
#pragma unroll
        for (int mi = 0; mi < 2; mi++) {
#pragma unroll
            for (int nn = 0; nn < 4; nn++) {
                int c0 = wn * 32 + nn * 8 + (lane & 3) * 2;
                float w30 = w3s[c0], w31 = w3s[c0 + 1];
                float bb0 = b2s[c0], bb1 = b2s[c0 + 1];
                part[mi][0] += fmaxf(acc[mi][nn][0] + bb0, 0.f) * w30
                             + fmaxf(acc[mi][nn][1] + bb1, 0.f) * w31;
                part[mi][1] += fmaxf(acc[mi][nn][2] + bb0, 0.f) * w30
                             + fmaxf(acc[mi][nn][3] + bb1, 0.f) * w31;
            }
        }
#pragma unroll
        for (int mi = 0; mi < 2; mi++) {
#pragma unroll
            for (int g = 0; g < 2; g++) {
                part[mi][g] += __shfl_xor_sync(0xffffffffu, part[mi][g], 1);
                part[mi][g] += __shfl_xor_sync(0xffffffffu, part[mi][g], 2);
            }
        }
        if ((lane & 3) == 0) {
            float* pw = wn ? pb : pa;
            int r0 = wm * 32 + (lane >> 2);
            pw[r0]      = part[0][0];
            pw[r0 + 8]  = part[0][1];
            pw[r0 + 16] = part[1][0];
            pw[r0 + 24] = part[1][1];
        }
        __syncthreads();
        if (t < 128) out[eb_id[t]] = pa[t] + pb[t] + be3v;
        buf ^= 1;
    }
}

// ---------------- launch ----------------
extern "C" void kernel_launch(void* const* d_in, const int* in_sizes, int n_in,
                              void* d_out, int out_size) {
    const float* x   = (const float*)d_in[0];
    const int*   ei  = (const int*)d_in[1];
    const float* ea  = (const float*)d_in[2];
    const float* w1r = (const float*)d_in[3];
    const float* w1n = (const float*)d_in[4];
    const float* b1  = (const float*)d_in[5];
    const float* w2r = (const float*)d_in[6];
    const float* w2n = (const float*)d_in[7];
    const float* b2  = (const float*)d_in[8];
    const float* we1 = (const float*)d_in[9];
    const float* be1 = (const float*)d_in[10];
    const float* we2 = (const float*)d_in[11];
    const float* be2 = (const float*)d_in[12];
    const float* we3 = (const float*)d_in[13];
    const float* be3 = (const float*)d_in[14];
    float* out = (float*)d_out;

    cudaFuncSetAttribute(k_h2_tf32, cudaFuncAttributeMaxDynamicSharedMemorySize,
                         H2_TOTAL);
    cudaFuncSetAttribute(k_pq_tf32, cudaFuncAttributeMaxDynamicSharedMemorySize,
                         PQ_TOTAL);
    cudaFuncSetAttribute(k_edge_tf32, cudaFuncAttributeMaxDynamicSharedMemorySize,
                         SM_EDGE_TOTAL);

    // CSR build
    k_zero_deg<<<SCAN_B, 1024>>>();
    k_hist<<<N_EDGES / 256, 256>>>(ei);
    k_scan1<<<SCAN_B, 1024>>>();
    k_scan2<<<1, 128>>>();
    k_scan3<<<SCAN_B, 1024>>>();
    k_scatter<<<N_EDGES / 256, 256>>>(ei);
    // node pipeline
    k_h1g<<<N_NODES / 8, 256>>>(x, w1r, w1n, b1);
    k_gather2<<<N_NODES / 8, 256>>>();
    k_h2_tf32<<<dim3((N_NODES + 63) / 64, 2), 256, H2_TOTAL>>>(w2r, w2n, b2);
    k_pq_tf32<<<dim3((N_NODES + 63) / 64, 4), 256, PQ_TOTAL>>>(we1);
    // edge pipeline
    k_edge_tf32<<<EDGE_GRID, 256, SM_EDGE_TOTAL>>>(ea, we1, be1, we2, be2, we3, be3, out);
}